// round 4
// baseline (speedup 1.0000x reference)
#include <cuda_runtime.h>
#include <cstdint>

// Problem dims (fixed)
#define BB   64
#define TT   512
#define IDIM 256
#define HH   512
#define BTH  (BB*TT*HH)

// Recurrence decomposition: 16 clusters (batch groups) x 8 CTAs (column groups)
#define GB   16
#define GC   8
#define BPG  4           // batches per group
#define CPG  64          // columns per CTA
#define NCTA (GB*GC)
#define THR  512         // threads per recurrence CTA (16 warps)

// ------------------------------ scratch ------------------------------------
__device__ float g_xb[TT*BB*HH];      // input projection, time-major [t][b][h]
__device__ float g_out0[BB*TT*HH];    // layer-0 output [b][t][h]

// ------------------------------ input GEMM ----------------------------------
#define SSTR 68

__global__ void __launch_bounds__(256) gemm_ih(
    const float* __restrict__ Xin,
    const float* __restrict__ W,
    const float* __restrict__ b1,
    const float* __restrict__ b2,
    int K, int use_g0)
{
    __shared__ float As[16 * SSTR];
    __shared__ float Bs[16 * SSTR];

    const float* X = use_g0 ? g_out0 : Xin;

    const int tid = threadIdx.x;
    const int tx  = tid & 15;
    const int ty  = tid >> 4;
    const int nb  = blockIdx.x;
    const int mb  = blockIdx.y;
    const int ar  = tid >> 2;
    const int ac  = tid & 3;

    const float* Xrow = X + (size_t)(mb * 64 + ar) * K;
    const float* Wrow = W + (size_t)(nb * 64 + ar) * K;

    float acc[4][4];
#pragma unroll
    for (int i = 0; i < 4; i++)
#pragma unroll
        for (int j = 0; j < 4; j++) acc[i][j] = 0.f;

    for (int k0 = 0; k0 < K; k0 += 16) {
        float4 av = *reinterpret_cast<const float4*>(Xrow + k0 + ac * 4);
        float4 bv = *reinterpret_cast<const float4*>(Wrow + k0 + ac * 4);
        As[(ac * 4 + 0) * SSTR + ar] = av.x;
        As[(ac * 4 + 1) * SSTR + ar] = av.y;
        As[(ac * 4 + 2) * SSTR + ar] = av.z;
        As[(ac * 4 + 3) * SSTR + ar] = av.w;
        Bs[(ac * 4 + 0) * SSTR + ar] = bv.x;
        Bs[(ac * 4 + 1) * SSTR + ar] = bv.y;
        Bs[(ac * 4 + 2) * SSTR + ar] = bv.z;
        Bs[(ac * 4 + 3) * SSTR + ar] = bv.w;
        __syncthreads();

#pragma unroll
        for (int kk = 0; kk < 16; kk++) {
            float4 a4 = *reinterpret_cast<const float4*>(&As[kk * SSTR + ty * 4]);
            float4 b4 = *reinterpret_cast<const float4*>(&Bs[kk * SSTR + tx * 4]);
            float aa[4] = {a4.x, a4.y, a4.z, a4.w};
            float bb[4] = {b4.x, b4.y, b4.z, b4.w};
#pragma unroll
            for (int i = 0; i < 4; i++)
#pragma unroll
                for (int j = 0; j < 4; j++)
                    acc[i][j] += aa[i] * bb[j];
        }
        __syncthreads();
    }

    const int n0 = nb * 64 + tx * 4;
    float4 bias;
    bias.x = b1[n0 + 0] + b2[n0 + 0];
    bias.y = b1[n0 + 1] + b2[n0 + 1];
    bias.z = b1[n0 + 2] + b2[n0 + 2];
    bias.w = b1[n0 + 3] + b2[n0 + 3];

#pragma unroll
    for (int i = 0; i < 4; i++) {
        int m  = mb * 64 + ty * 4 + i;
        int b_ = m >> 9;
        int t_ = m & (TT - 1);
        float4 o;
        o.x = acc[i][0] + bias.x;
        o.y = acc[i][1] + bias.y;
        o.z = acc[i][2] + bias.z;
        o.w = acc[i][3] + bias.w;
        *reinterpret_cast<float4*>(&g_xb[((size_t)t_ * BB + b_) * HH + n0]) = o;
    }
}

// ------------------------------ helpers -------------------------------------
__device__ __forceinline__ uint32_t smem_u32(const void* p) {
    uint32_t a;
    asm("{ .reg .u64 t; cvta.to.shared.u64 t, %1; cvt.u32.u64 %0, t; }"
        : "=r"(a) : "l"(p));
    return a;
}

__device__ __forceinline__ void mbar_wait_cluster(uint32_t mbar, uint32_t parity) {
    asm volatile(
        "{\n\t"
        ".reg .pred P;\n\t"
        "WL%=:\n\t"
        "mbarrier.try_wait.parity.acquire.cluster.shared::cta.b64 P, [%0], %1;\n\t"
        "@!P bra WL%=;\n\t"
        "}"
        :: "r"(mbar), "r"(parity) : "memory");
}

// ------------------------------ recurrence ----------------------------------
// h_{t+1}[b,c] = tanh(xb[t][b][c] + sum_k h_t[b,k] * Whh[c,k])
// Cluster of 8 CTAs per batch group. State hb[k] = float4 of 4 batches; each
// CTA produces k in [c0,c0+64) = one contiguous 1KB block, broadcast to all
// 8 cluster CTAs via cp.async.bulk S->S (1KB each) completing split mbarriers
// (A: src ranks 0-3 = k<256, B: src ranks 4-7 = k>=256). Warps needing only
// low k wait on A and start while B's bytes are still in flight.
//
// smem floats: Wt[512*64] | hb[2][512]f4 | hst[2][64]f4 | red[32][256] | mbar u64[4]
#define SMF_HB   (HH*CPG)                 // 32768
#define SMF_HST  (SMF_HB + 2*HH*4)        // 36864
#define SMF_RED  (SMF_HST + 2*CPG*4)      // 37376
#define SMF_MBAR (SMF_RED + 32*256)       // 45568
#define REC_SMEM_BYTES ((SMF_MBAR + 8) * 4)   // 182304 B

#define HALF_TX  4096u    // 4 ranks x 1KB per mbarrier per phase

__global__ void __launch_bounds__(THR, 1) __cluster_dims__(GC, 1, 1)
rnn_rec(const float* __restrict__ Whh,
        const float* __restrict__ h0,
        float* __restrict__ out_param,
        float* __restrict__ hn,
        int use_g0out)
{
    extern __shared__ float sm[];
    float*  Wt   = sm;                                      // [k][c]
    float4* hb   = reinterpret_cast<float4*>(sm + SMF_HB);  // [2][512]
    float*  hstf = sm + SMF_HST;                            // [2][256]
    float*  red  = sm + SMF_RED;                            // [32][256]

    const int tid = threadIdx.x;
    uint32_t cg;
    asm("mov.u32 %0, %%cluster_ctarank;" : "=r"(cg));
    const int bg  = blockIdx.x >> 3;
    const int c0  = (int)cg * CPG;
    const int b0  = bg * BPG;
    const int ks  = tid >> 4;        // K-slice 0..31 (16 k each)
    const int cq  = tid & 15;        // column quad
    const int ob  = tid >> 6;        // (valid for tid<256) output batch 0..3
    const int oc  = tid & 63;        // output column 0..63
    const bool lowhalf = (tid < 256);    // warps 0-7: k < 256

    float* outp = use_g0out ? g_out0 : out_param;

    const uint32_t mbar_u = smem_u32(sm + SMF_MBAR);  // u64[4]: A0 A1 B0 B1
    const uint32_t hb_u   = smem_u32(hb);
    const uint32_t hst_u  = smem_u32(hstf);

    // Load W slice transposed: Wt[k][c] = Whh[c0+c][k].
    for (int idx = tid; idx < CPG * (HH / 4); idx += THR) {
        int c  = idx & (CPG - 1);
        int k4 = idx >> 6;
        float4 w = *reinterpret_cast<const float4*>(Whh + (size_t)(c0 + c) * HH + k4 * 4);
        Wt[(k4 * 4 + 0) * CPG + c] = w.x;
        Wt[(k4 * 4 + 1) * CPG + c] = w.y;
        Wt[(k4 * 4 + 2) * CPG + c] = w.z;
        Wt[(k4 * 4 + 3) * CPG + c] = w.w;
    }
    // Init hb[0][k] = float4 over the 4 batches of this group.
    {
        int k = tid;   // 0..511
        hb[k] = make_float4(h0[(size_t)(b0 + 0) * HH + k],
                            h0[(size_t)(b0 + 1) * HH + k],
                            h0[(size_t)(b0 + 2) * HH + k],
                            h0[(size_t)(b0 + 3) * HH + k]);
    }
    if (tid == 0) {
#pragma unroll
        for (int i = 0; i < 4; i++) {
            uint32_t m = mbar_u + i * 8;
            asm volatile("mbarrier.init.shared.b64 [%0], %1;" :: "r"(m), "r"(1u) : "memory");
            asm volatile("mbarrier.arrive.expect_tx.shared.b64 _, [%0], %1;"
                         :: "r"(m), "r"(HALF_TX) : "memory");
        }
    }
    __syncthreads();
    asm volatile("barrier.cluster.arrive.aligned;" ::: "memory");
    asm volatile("barrier.cluster.wait.aligned;"   ::: "memory");

    const uint32_t myM       = mbar_u + (lowhalf ? 0u : 16u);  // mbar I wait on
    const uint32_t send_off  = (cg < 4) ? 0u : 16u;            // mbar class I complete
    uint32_t ph[2] = {0, 0};

    for (int t = 0; t < TT; ++t) {
        const int p = t & 1;

        // Prefetch input projection (independent of h).
        float xbv = 0.f;
        if (tid < 256)
            xbv = __ldcg(&g_xb[((size_t)t * BB + (b0 + ob)) * HH + c0 + oc]);

        if (t > 0) {
            mbar_wait_cluster(myM + (uint32_t)p * 8, ph[p]);
            ph[p] ^= 1;
            // re-arm for reuse at t+2
            if (tid == 0)
                asm volatile("mbarrier.arrive.expect_tx.shared.b64 _, [%0], %1;"
                             :: "r"(mbar_u + (uint32_t)p * 8), "r"(HALF_TX) : "memory");
            if (tid == 256)
                asm volatile("mbarrier.arrive.expect_tx.shared.b64 _, [%0], %1;"
                             :: "r"(mbar_u + 16u + (uint32_t)p * 8), "r"(HALF_TX) : "memory");
        }
        // hst[p] gets overwritten below; ensure the copy issued at t-2 (which
        // read hst[p]) has finished reading. (<=1 outstanding group allowed.)
        if (tid == 0)
            asm volatile("cp.async.bulk.wait_group.read 1;" ::: "memory");

        const float4* hbp = hb + p * HH;

        // 4 batches x 4 cols register tile over this thread's 16-k slice.
        float acc[4][4];
#pragma unroll
        for (int i = 0; i < 4; i++)
#pragma unroll
            for (int j = 0; j < 4; j++) acc[i][j] = 0.f;

        const int kb = ks * 16;
#pragma unroll
        for (int kc = 0; kc < 16; ++kc) {
            const int k = kb + kc;
            float4 h4 = hbp[k];
            float4 w4 = *reinterpret_cast<const float4*>(&Wt[k * CPG + cq * 4]);
            float hk[4] = {h4.x, h4.y, h4.z, h4.w};
            float wj[4] = {w4.x, w4.y, w4.z, w4.w};
#pragma unroll
            for (int b = 0; b < 4; b++)
#pragma unroll
                for (int j = 0; j < 4; j++)
                    acc[b][j] += hk[b] * wj[j];
        }

#pragma unroll
        for (int b = 0; b < 4; ++b)
            *reinterpret_cast<float4*>(&red[ks * 256 + b * 64 + cq * 4]) =
                make_float4(acc[b][0], acc[b][1], acc[b][2], acc[b][3]);
        __syncthreads();   // S1

        if (tid < 256) {
            float s = 0.f;
#pragma unroll
            for (int k2 = 0; k2 < 32; ++k2) s += red[k2 * 256 + tid];
            float v = tanhf(s + xbv);

            outp[((size_t)(b0 + ob) * TT + t) * HH + c0 + oc] = v;
            if (t == TT - 1) hn[(size_t)(b0 + ob) * HH + c0 + oc] = v;

            if (t < TT - 1) {
                hstf[p * 256 + oc * 4 + ob] = v;   // staging: [oc] x float4(batch)
                asm volatile("fence.proxy.async.shared::cta;" ::: "memory");
            }
        }
        __syncthreads();   // S2: hst visible; also orders red reuse & mbar gating

        // Elected thread broadcasts our 1KB block to all 8 cluster CTAs.
        if (t < TT - 1 && tid == 0) {
            const int p1 = p ^ 1;
            const uint32_t src   = hst_u + (uint32_t)(p * 1024);
            const uint32_t dst_l = hb_u + (uint32_t)(p1 * 8192) + (uint32_t)(c0 * 16);
            const uint32_t mbr_l = mbar_u + send_off + (uint32_t)(p1 * 8);
#pragma unroll
            for (int r = 0; r < GC; ++r) {
                uint32_t da, ma;
                asm("mapa.shared::cluster.u32 %0, %1, %2;" : "=r"(da) : "r"(dst_l), "r"(r));
                asm("mapa.shared::cluster.u32 %0, %1, %2;" : "=r"(ma) : "r"(mbr_l), "r"(r));
                asm volatile(
                    "cp.async.bulk.shared::cluster.shared::cta.mbarrier::complete_tx::bytes "
                    "[%0], [%1], %2, [%3];"
                    :: "r"(da), "r"(src), "r"(1024u), "r"(ma) : "memory");
            }
            asm volatile("cp.async.bulk.commit_group;" ::: "memory");
        }
    }

    if (tid == 0)
        asm volatile("cp.async.bulk.wait_group.read 0;" ::: "memory");
    asm volatile("barrier.cluster.arrive.aligned;" ::: "memory");
    asm volatile("barrier.cluster.wait.aligned;"   ::: "memory");
}

// ------------------------------ launch --------------------------------------
extern "C" void kernel_launch(void* const* d_in, const int* in_sizes, int n_in,
                              void* d_out, int out_size)
{
    const float* x    = (const float*)d_in[0];
    const float* h0   = (const float*)d_in[1];   // [2, B, H]
    const float* Wih0 = (const float*)d_in[2];
    const float* Whh0 = (const float*)d_in[3];
    const float* bih0 = (const float*)d_in[4];
    const float* bhh0 = (const float*)d_in[5];
    const float* Wih1 = (const float*)d_in[6];
    const float* Whh1 = (const float*)d_in[7];
    const float* bih1 = (const float*)d_in[8];
    const float* bhh1 = (const float*)d_in[9];

    float* out  = (float*)d_out;
    float* out1 = out;                       // [B,T,H]
    float* hn0  = out + (size_t)BTH;         // h_n[0]
    float* hn1  = hn0 + (size_t)BB * HH;     // h_n[1]

    static int smem_set = 0;
    if (!smem_set) {
        cudaFuncSetAttribute(rnn_rec, cudaFuncAttributeMaxDynamicSharedMemorySize,
                             REC_SMEM_BYTES);
        smem_set = 1;
    }

    dim3 ggrid(HH / 64, (BB * TT) / 64);     // (8, 512)

    gemm_ih<<<ggrid, 256>>>(x, Wih0, bih0, bhh0, IDIM, 0);
    rnn_rec<<<NCTA, THR, REC_SMEM_BYTES>>>(Whh0, h0, nullptr, hn0, 1);
    gemm_ih<<<ggrid, 256>>>(nullptr, Wih1, bih1, bhh1, HH, 1);
    rnn_rec<<<NCTA, THR, REC_SMEM_BYTES>>>(Whh1, h0 + (size_t)BB * HH, out1, hn1, 0);
}